// round 3
// baseline (speedup 1.0000x reference)
#include <cuda_runtime.h>
#include <math.h>

#define H 4
#define Bb 8
#define Nn 1024
#define INF_ 1024
#define E 256
#define A_ 64
#define BN_ROWS 8192        /* B*N */
#define ALPHA 0.2f
#define UNIF (1.0f/1024.0f)

// ---- scratch (static device memory; no runtime allocation) ----
__device__ float g_Wh[H * BN_ROWS * E];                 // 32 MB   [h][row][e]
__device__ float g_f1[H * BN_ROWS];
__device__ float g_f2[H * BN_ROWS];
__device__ float g_E1[H * BN_ROWS];                     // exp(f1)
__device__ float g_F1[H * BN_ROWS];                     // exp(0.2*f1)
__device__ float g_E2[H * BN_ROWS];                     // exp(f2)
__device__ float g_F2[H * BN_ROWS];                     // exp(0.2*f2)
__device__ float g_inv[H * BN_ROWS];                    // 1/rowsum, or -1 sentinel
__device__ unsigned g_adjbits[Bb * Nn * (Nn / 32)];     // 1 MB packed adjacency
__device__ float g_feat[(size_t)BN_ROWS * H * E];       // 32 MB  [row][h*E+e]

// ============================================================
// K0: pack adjacency int32 -> bitmask (1 bit / edge)
// ============================================================
__global__ void pack_adj(const int* __restrict__ adj) {
    int idx = blockIdx.x * blockDim.x + threadIdx.x;   // 0 .. 8M-1
    unsigned m = __ballot_sync(0xffffffffu, adj[idx] > 0);
    if ((idx & 31) == 0) g_adjbits[idx >> 5] = m;
}

// ============================================================
// K1: Wh[h] (8192 x 256) = x (8192 x 1024) @ W[h] (1024 x 256)
// ============================================================
__global__ void wh_gemm(const float* __restrict__ x, const float* __restrict__ W) {
    const int BM = 128, BNc = 64, BK = 16;
    __shared__ float As[BK][BM];
    __shared__ float Bs[BK][BNc];
    int h = blockIdx.z;
    int rowBase = blockIdx.y * BM;
    int colBase = blockIdx.x * BNc;
    const float* Bp = W + (size_t)h * INF_ * E;
    int tid = threadIdx.x;
    int tx = tid & 15, ty = tid >> 4;
    float acc[8][4] = {};
    for (int k0 = 0; k0 < INF_; k0 += BK) {
#pragma unroll
        for (int l = 0; l < 2; l++) {
            int f = tid + l * 256;
            int r = f >> 2, c4 = f & 3;
            float4 v = *(const float4*)(x + (size_t)(rowBase + r) * INF_ + k0 + c4 * 4);
            As[c4 * 4 + 0][r] = v.x;
            As[c4 * 4 + 1][r] = v.y;
            As[c4 * 4 + 2][r] = v.z;
            As[c4 * 4 + 3][r] = v.w;
        }
        {
            int r = tid >> 4, c4 = tid & 15;
            float4 v = *(const float4*)(Bp + (size_t)(k0 + r) * E + colBase + c4 * 4);
            *(float4*)&Bs[r][c4 * 4] = v;
        }
        __syncthreads();
#pragma unroll
        for (int kk = 0; kk < BK; kk++) {
            float a[8], b[4];
#pragma unroll
            for (int i = 0; i < 8; i++) a[i] = As[kk][ty * 8 + i];
            float4 bv = *(float4*)&Bs[kk][tx * 4];
            b[0] = bv.x; b[1] = bv.y; b[2] = bv.z; b[3] = bv.w;
#pragma unroll
            for (int i = 0; i < 8; i++)
#pragma unroll
                for (int j = 0; j < 4; j++) acc[i][j] += a[i] * b[j];
        }
        __syncthreads();
    }
    float* Cp = g_Wh + (size_t)h * BN_ROWS * E;
#pragma unroll
    for (int i = 0; i < 8; i++) {
        int r = rowBase + ty * 8 + i;
        float4 v = make_float4(acc[i][0], acc[i][1], acc[i][2], acc[i][3]);
        *(float4*)(Cp + (size_t)r * E + colBase + tx * 4) = v;
    }
}

// ============================================================
// K2: f1/f2 = Wh . a1 / a2, plus the 4 factored exponentials
// ============================================================
__global__ void compute_f(const float* __restrict__ a1, const float* __restrict__ a2) {
    int r = blockIdx.x;                 // 0 .. H*BN_ROWS-1
    int h = r / BN_ROWS;
    int t = threadIdx.x;
    float v = g_Wh[(size_t)r * E + t];
    float s1 = v * a1[h * E + t];
    float s2 = v * a2[h * E + t];
#pragma unroll
    for (int o = 16; o > 0; o >>= 1) {
        s1 += __shfl_xor_sync(0xffffffffu, s1, o);
        s2 += __shfl_xor_sync(0xffffffffu, s2, o);
    }
    __shared__ float r1[8], r2[8];
    if ((t & 31) == 0) { r1[t >> 5] = s1; r2[t >> 5] = s2; }
    __syncthreads();
    if (t == 0) {
        float a = 0.f, b = 0.f;
#pragma unroll
        for (int i = 0; i < 8; i++) { a += r1[i]; b += r2[i]; }
        g_f1[r] = a;
        g_f2[r] = b;
        g_E1[r] = __expf(a);
        g_F1[r] = __expf(ALPHA * a);
        g_E2[r] = __expf(b);
        g_F2[r] = __expf(ALPHA * b);
    }
}

// ============================================================
// K3: per-row softmax normalizer:
//   sum_j adj_ij * (s>0 ? E1_i*E2_j : F1_i*F2_j),  inv = 1/sum (or -1 sentinel)
// ============================================================
__global__ void rowsum() {
    int i = blockIdx.x, b = blockIdx.y, h = blockIdx.z;
    int t = threadIdx.x;
    int base = h * BN_ROWS + b * Nn;
    float f1v = g_f1[base + i];
    float E1v = g_E1[base + i];
    float F1v = g_F1[base + i];
    const unsigned* aw = g_adjbits + (size_t)(b * Nn + i) * (Nn / 32);
    float sum = 0.f;
#pragma unroll
    for (int l = 0; l < 4; l++) {
        int j = t + l * 256;
        unsigned w = aw[j >> 5];
        if ((w >> (j & 31)) & 1u) {
            float s = f1v + g_f2[base + j];
            sum += (s > 0.f) ? E1v * g_E2[base + j] : F1v * g_F2[base + j];
        }
    }
#pragma unroll
    for (int o = 16; o > 0; o >>= 1) sum += __shfl_xor_sync(0xffffffffu, sum, o);
    __shared__ float sm[8];
    if ((t & 31) == 0) sm[t >> 5] = sum;
    __syncthreads();
    if (t == 0) {
        float s = 0.f;
#pragma unroll
        for (int k = 0; k < 8; k++) s += sm[k];
        g_inv[base + i] = (s > 0.f) ? (1.0f / s) : -1.0f;
    }
}

// ============================================================
// K4: h' = att @ Wh_b with att generated on the fly, elu, transposed store
// grid (E/64, Nn/128, H*Bb)
// ============================================================
__global__ void att_gemm() {
    const int BM = 128, BNc = 64, BK = 16;
    __shared__ float As[BK][BM];
    __shared__ float Bs[BK][BNc];
    int hb = blockIdx.z;
    int h = hb / Bb, b = hb % Bb;
    int rowBase = blockIdx.y * BM;
    int colBase = blockIdx.x * BNc;
    int base = h * BN_ROWS + b * Nn;                    // f-array base for this (h,b)
    const float* Bp = g_Wh + ((size_t)h * BN_ROWS + b * Nn) * E;
    int tid = threadIdx.x;
    int tx = tid & 15, ty = tid >> 4;

    // per-thread row constants for on-the-fly att generation
    int r0 = tid >> 2;              // l=0 row (0..63)
    int r1 = r0 + 64;               // l=1 row
    int c4 = tid & 3;
    int gi0 = base + rowBase + r0;
    int gi1 = base + rowBase + r1;
    float f1_0 = g_f1[gi0], E1_0 = g_E1[gi0], F1_0 = g_F1[gi0], inv0 = g_inv[gi0];
    float f1_1 = g_f1[gi1], E1_1 = g_E1[gi1], F1_1 = g_F1[gi1], inv1 = g_inv[gi1];
    const unsigned* aw0 = g_adjbits + (size_t)(b * Nn + rowBase + r0) * (Nn / 32);
    const unsigned* aw1 = g_adjbits + (size_t)(b * Nn + rowBase + r1) * (Nn / 32);

    float acc[8][4] = {};
    for (int k0 = 0; k0 < Nn; k0 += BK) {
        int j0 = k0 + c4 * 4;
        float4 f2v = *(const float4*)(g_f2 + base + j0);
        float4 E2v = *(const float4*)(g_E2 + base + j0);
        float4 F2v = *(const float4*)(g_F2 + base + j0);
        unsigned w0 = aw0[j0 >> 5];
        unsigned w1 = aw1[j0 >> 5];
        int sh = j0 & 31;
        {
            float s, n, v;
            s = f1_0 + f2v.x; n = (s > 0.f) ? E1_0 * E2v.x : F1_0 * F2v.x;
            v = ((w0 >> (sh + 0)) & 1u) ? n * inv0 : 0.f; if (inv0 < 0.f) v = UNIF;
            As[c4 * 4 + 0][r0] = v;
            s = f1_0 + f2v.y; n = (s > 0.f) ? E1_0 * E2v.y : F1_0 * F2v.y;
            v = ((w0 >> (sh + 1)) & 1u) ? n * inv0 : 0.f; if (inv0 < 0.f) v = UNIF;
            As[c4 * 4 + 1][r0] = v;
            s = f1_0 + f2v.z; n = (s > 0.f) ? E1_0 * E2v.z : F1_0 * F2v.z;
            v = ((w0 >> (sh + 2)) & 1u) ? n * inv0 : 0.f; if (inv0 < 0.f) v = UNIF;
            As[c4 * 4 + 2][r0] = v;
            s = f1_0 + f2v.w; n = (s > 0.f) ? E1_0 * E2v.w : F1_0 * F2v.w;
            v = ((w0 >> (sh + 3)) & 1u) ? n * inv0 : 0.f; if (inv0 < 0.f) v = UNIF;
            As[c4 * 4 + 3][r0] = v;

            s = f1_1 + f2v.x; n = (s > 0.f) ? E1_1 * E2v.x : F1_1 * F2v.x;
            v = ((w1 >> (sh + 0)) & 1u) ? n * inv1 : 0.f; if (inv1 < 0.f) v = UNIF;
            As[c4 * 4 + 0][r1] = v;
            s = f1_1 + f2v.y; n = (s > 0.f) ? E1_1 * E2v.y : F1_1 * F2v.y;
            v = ((w1 >> (sh + 1)) & 1u) ? n * inv1 : 0.f; if (inv1 < 0.f) v = UNIF;
            As[c4 * 4 + 1][r1] = v;
            s = f1_1 + f2v.z; n = (s > 0.f) ? E1_1 * E2v.z : F1_1 * F2v.z;
            v = ((w1 >> (sh + 2)) & 1u) ? n * inv1 : 0.f; if (inv1 < 0.f) v = UNIF;
            As[c4 * 4 + 2][r1] = v;
            s = f1_1 + f2v.w; n = (s > 0.f) ? E1_1 * E2v.w : F1_1 * F2v.w;
            v = ((w1 >> (sh + 3)) & 1u) ? n * inv1 : 0.f; if (inv1 < 0.f) v = UNIF;
            As[c4 * 4 + 3][r1] = v;
        }
        {
            int r = tid >> 4, cc = tid & 15;
            float4 v = *(const float4*)(Bp + (size_t)(k0 + r) * E + colBase + cc * 4);
            *(float4*)&Bs[r][cc * 4] = v;
        }
        __syncthreads();
#pragma unroll
        for (int kk = 0; kk < BK; kk++) {
            float a[8], bv2[4];
#pragma unroll
            for (int i = 0; i < 8; i++) a[i] = As[kk][ty * 8 + i];
            float4 bv = *(float4*)&Bs[kk][tx * 4];
            bv2[0] = bv.x; bv2[1] = bv.y; bv2[2] = bv.z; bv2[3] = bv.w;
#pragma unroll
            for (int i = 0; i < 8; i++)
#pragma unroll
                for (int j = 0; j < 4; j++) acc[i][j] += a[i] * bv2[j];
        }
        __syncthreads();
    }
    // epilogue: elu, write to feat[(b*Nn + r)][h*E + col]
#pragma unroll
    for (int i = 0; i < 8; i++) {
        int r = rowBase + ty * 8 + i;
        float4 v;
        float t0 = acc[i][0], t1 = acc[i][1], t2 = acc[i][2], t3 = acc[i][3];
        v.x = t0 > 0.f ? t0 : expm1f(t0);
        v.y = t1 > 0.f ? t1 : expm1f(t1);
        v.z = t2 > 0.f ? t2 : expm1f(t2);
        v.w = t3 > 0.f ? t3 : expm1f(t3);
        *(float4*)(g_feat + (size_t)(b * Nn + r) * (H * E) + h * E + colBase + tx * 4) = v;
    }
}

// ============================================================
// K5: out (8192x64) = feat (8192x1024) @ W_act (1024x64) + b_act
// ============================================================
__global__ void final_gemm(const float* __restrict__ W_act,
                           const float* __restrict__ b_act,
                           float* __restrict__ out) {
    const int BM = 64, BK = 16;
    __shared__ float As[BK][BM];
    __shared__ float Bs[BK][A_];
    int rowBase = blockIdx.y * BM;
    int tid = threadIdx.x;
    int tx = tid & 15, ty = tid >> 4;
    float acc[4][4] = {};
    for (int k0 = 0; k0 < H * E; k0 += BK) {
        {
            int r = tid >> 2, c4 = tid & 3;
            float4 v = *(const float4*)(g_feat + (size_t)(rowBase + r) * (H * E) + k0 + c4 * 4);
            As[c4 * 4 + 0][r] = v.x;
            As[c4 * 4 + 1][r] = v.y;
            As[c4 * 4 + 2][r] = v.z;
            As[c4 * 4 + 3][r] = v.w;
        }
        {
            int r = tid >> 4, c4 = tid & 15;
            float4 v = *(const float4*)(W_act + (size_t)(k0 + r) * A_ + c4 * 4);
            *(float4*)&Bs[r][c4 * 4] = v;
        }
        __syncthreads();
#pragma unroll
        for (int kk = 0; kk < BK; kk++) {
            float a[4], b[4];
#pragma unroll
            for (int i = 0; i < 4; i++) a[i] = As[kk][ty * 4 + i];
            float4 bv = *(float4*)&Bs[kk][tx * 4];
            b[0] = bv.x; b[1] = bv.y; b[2] = bv.z; b[3] = bv.w;
#pragma unroll
            for (int i = 0; i < 4; i++)
#pragma unroll
                for (int j = 0; j < 4; j++) acc[i][j] += a[i] * b[j];
        }
        __syncthreads();
    }
#pragma unroll
    for (int i = 0; i < 4; i++) {
        int r = rowBase + ty * 4 + i;
        float4 bias = *(const float4*)(b_act + tx * 4);
        float4 v = make_float4(acc[i][0] + bias.x, acc[i][1] + bias.y,
                               acc[i][2] + bias.z, acc[i][3] + bias.w);
        *(float4*)(out + (size_t)r * A_ + tx * 4) = v;
    }
}

extern "C" void kernel_launch(void* const* d_in, const int* in_sizes, int n_in,
                              void* d_out, int out_size) {
    const float* x     = (const float*)d_in[0];
    const int*   adj   = (const int*)d_in[1];
    const float* W     = (const float*)d_in[2];
    const float* a1    = (const float*)d_in[3];
    const float* a2    = (const float*)d_in[4];
    const float* W_act = (const float*)d_in[5];
    const float* b_act = (const float*)d_in[6];
    float* out = (float*)d_out;

    pack_adj<<<(Bb * Nn * Nn) / 256, 256>>>(adj);
    wh_gemm<<<dim3(E / 64, BN_ROWS / 128, H), 256>>>(x, W);
    compute_f<<<H * BN_ROWS, 256>>>(a1, a2);
    rowsum<<<dim3(Nn, Bb, H), 256>>>();
    att_gemm<<<dim3(E / 64, Nn / 128, H * Bb), 256>>>();
    final_gemm<<<dim3(1, BN_ROWS / 64), 256>>>(W_act, b_act, out);
}

// round 4
// speedup vs baseline: 1.1653x; 1.1653x over previous
#include <cuda_runtime.h>
#include <math.h>

#define H 4
#define Bb 8
#define Nn 1024
#define INF_ 1024
#define E 256
#define A_ 64
#define BN_ROWS 8192        /* B*N */
#define ALPHA 0.2f

// ---- scratch (static device memory; no runtime allocation) ----
__device__ float g_Wh[H * BN_ROWS * E];                 // 32 MB   [h][row][e]
__device__ float g_f1[H * BN_ROWS];
__device__ float g_f2[H * BN_ROWS];
__device__ float g_E1[H * BN_ROWS];                     // exp(f1)
__device__ float g_F1[H * BN_ROWS];                     // exp(0.2*f1)
__device__ float g_E2[H * BN_ROWS];                     // exp(f2)
__device__ float g_F2[H * BN_ROWS];                     // exp(0.2*f2)
__device__ unsigned g_adjbits[Bb * Nn * (Nn / 32)];     // 1 MB packed adjacency
__device__ float g_feat[(size_t)BN_ROWS * H * E];       // 32 MB  [row][h*E+e]

// ============================================================
// K0: pack adjacency int32 -> bitmask
// ============================================================
__global__ void pack_adj(const int* __restrict__ adj) {
    int idx = blockIdx.x * blockDim.x + threadIdx.x;
    unsigned m = __ballot_sync(0xffffffffu, adj[idx] > 0);
    if ((idx & 31) == 0) g_adjbits[idx >> 5] = m;
}

// ============================================================
// K1: Wh[h] (8192x256) = x (8192x1024) @ W[h] (1024x256)
// 128x128x16 double-buffered, 256 threads, 8x8 microtile (4+4 split)
// grid (E/128=2, 8192/128=64, H=4)
// ============================================================
__global__ void __launch_bounds__(256) wh_gemm(const float* __restrict__ x,
                                               const float* __restrict__ W) {
    __shared__ float As[2][16][128];
    __shared__ float Bs[2][16][128];
    int h = blockIdx.z;
    int rowBase = blockIdx.y * 128;
    int colBase = blockIdx.x * 128;
    const float* Bp = W + (size_t)h * INF_ * E;
    int tid = threadIdx.x;
    int tx = tid & 15, ty = tid >> 4;

    // A loads: rows ar, ar+64; k slice ak..ak+3
    int ar = tid >> 2, ak = (tid & 3) * 4;
    // B loads: rows bk, bk+8; cols bn..bn+3
    int bk = tid >> 5, bn = (tid & 31) * 4;

    const float* Arow0 = x + (size_t)(rowBase + ar) * INF_;
    const float* Arow1 = x + (size_t)(rowBase + ar + 64) * INF_;

    float4 a0 = *(const float4*)(Arow0 + ak);
    float4 a1v = *(const float4*)(Arow1 + ak);
    float4 b0 = *(const float4*)(Bp + (size_t)bk * E + colBase + bn);
    float4 b1 = *(const float4*)(Bp + (size_t)(bk + 8) * E + colBase + bn);

    As[0][ak + 0][ar] = a0.x; As[0][ak + 1][ar] = a0.y;
    As[0][ak + 2][ar] = a0.z; As[0][ak + 3][ar] = a0.w;
    As[0][ak + 0][ar + 64] = a1v.x; As[0][ak + 1][ar + 64] = a1v.y;
    As[0][ak + 2][ar + 64] = a1v.z; As[0][ak + 3][ar + 64] = a1v.w;
    *(float4*)&Bs[0][bk][bn] = b0;
    *(float4*)&Bs[0][bk + 8][bn] = b1;
    __syncthreads();

    float acc[8][8] = {};
    int buf = 0;
    for (int k0 = 16;; k0 += 16) {
        bool last = (k0 >= INF_);
        if (!last) {
            a0  = *(const float4*)(Arow0 + k0 + ak);
            a1v = *(const float4*)(Arow1 + k0 + ak);
            b0  = *(const float4*)(Bp + (size_t)(k0 + bk) * E + colBase + bn);
            b1  = *(const float4*)(Bp + (size_t)(k0 + bk + 8) * E + colBase + bn);
        }
#pragma unroll
        for (int kk = 0; kk < 16; kk++) {
            float a[8], b[8];
            *(float4*)(a)     = *(float4*)&As[buf][kk][ty * 4];
            *(float4*)(a + 4) = *(float4*)&As[buf][kk][64 + ty * 4];
            *(float4*)(b)     = *(float4*)&Bs[buf][kk][tx * 4];
            *(float4*)(b + 4) = *(float4*)&Bs[buf][kk][64 + tx * 4];
#pragma unroll
            for (int i = 0; i < 8; i++)
#pragma unroll
                for (int j = 0; j < 8; j++) acc[i][j] += a[i] * b[j];
        }
        if (last) break;
        buf ^= 1;
        As[buf][ak + 0][ar] = a0.x; As[buf][ak + 1][ar] = a0.y;
        As[buf][ak + 2][ar] = a0.z; As[buf][ak + 3][ar] = a0.w;
        As[buf][ak + 0][ar + 64] = a1v.x; As[buf][ak + 1][ar + 64] = a1v.y;
        As[buf][ak + 2][ar + 64] = a1v.z; As[buf][ak + 3][ar + 64] = a1v.w;
        *(float4*)&Bs[buf][bk][bn] = b0;
        *(float4*)&Bs[buf][bk + 8][bn] = b1;
        __syncthreads();
    }

    float* Cp = g_Wh + (size_t)h * BN_ROWS * E;
#pragma unroll
    for (int i = 0; i < 8; i++) {
        int rl = (i < 4) ? (ty * 4 + i) : (64 + ty * 4 + i - 4);
        float* cr = Cp + (size_t)(rowBase + rl) * E + colBase;
        *(float4*)(cr + tx * 4)      = make_float4(acc[i][0], acc[i][1], acc[i][2], acc[i][3]);
        *(float4*)(cr + 64 + tx * 4) = make_float4(acc[i][4], acc[i][5], acc[i][6], acc[i][7]);
    }
}

// ============================================================
// K2: f1/f2 = Wh . a1/a2 + factored exps. Warp per row.
// grid 4096 x 256thr (8 warps = 8 rows per block)
// ============================================================
__global__ void compute_f(const float* __restrict__ a1, const float* __restrict__ a2) {
    int r = (blockIdx.x * blockDim.x + threadIdx.x) >> 5;  // 0 .. H*BN_ROWS-1
    int lane = threadIdx.x & 31;
    int h = r >> 13;                                       // /8192
    const float* wh = g_Wh + (size_t)r * E;
    const float* a1p = a1 + h * E;
    const float* a2p = a2 + h * E;
    float s1 = 0.f, s2 = 0.f;
#pragma unroll
    for (int i = 0; i < 8; i++) {
        int e = lane + i * 32;
        float v = wh[e];
        s1 += v * a1p[e];
        s2 += v * a2p[e];
    }
#pragma unroll
    for (int o = 16; o > 0; o >>= 1) {
        s1 += __shfl_xor_sync(0xffffffffu, s1, o);
        s2 += __shfl_xor_sync(0xffffffffu, s2, o);
    }
    if (lane == 0) {
        g_f1[r] = s1;
        g_f2[r] = s2;
        g_E1[r] = __expf(s1);
        g_F1[r] = __expf(ALPHA * s1);
        g_E2[r] = __expf(s2);
        g_F2[r] = __expf(ALPHA * s2);
    }
}

// ============================================================
// K3: h' = att @ Wh_b ; att generated on the fly (unnormalized),
// row-sums accumulated in registers, normalization + elu in epilogue.
// 128x128x16 double-buffered. grid (E/128=2, Nn/128=8, H*Bb=32)
// ============================================================
__global__ void __launch_bounds__(256) att_gemm() {
    __shared__ float As[2][16][128];
    __shared__ float Bs[2][16][128];
    __shared__ float Ssum[128];
    int hb = blockIdx.z;
    int h = hb >> 3, b = hb & 7;
    int rowBase = blockIdx.y * 128;
    int colBase = blockIdx.x * 128;
    int base = h * BN_ROWS + b * Nn;
    const float* Bp = g_Wh + ((size_t)h * BN_ROWS + b * Nn) * E;
    int tid = threadIdx.x;
    int tx = tid & 15, ty = tid >> 4;

    // generation assignment: rows ar, ar+64; j slice jq..jq+3
    int ar = tid >> 2, jq = (tid & 3) * 4;
    int gi0 = base + rowBase + ar;
    int gi1 = gi0 + 64;
    float f1_0 = g_f1[gi0], E1_0 = g_E1[gi0], F1_0 = g_F1[gi0];
    float f1_1 = g_f1[gi1], E1_1 = g_E1[gi1], F1_1 = g_F1[gi1];
    const unsigned* aw0 = g_adjbits + (size_t)(b * Nn + rowBase + ar) * (Nn / 32);
    const unsigned* aw1 = aw0 + (size_t)64 * (Nn / 32);

    // B loads
    int bk = tid >> 5, bn = (tid & 31) * 4;

    if (tid < 128) Ssum[tid] = 0.f;

    float rsum0 = 0.f, rsum1 = 0.f;

    // ---- prologue: generate tile 0 + load B tile 0
    float4 f2v = *(const float4*)(g_f2 + base + jq);
    float4 E2v = *(const float4*)(g_E2 + base + jq);
    float4 F2v = *(const float4*)(g_F2 + base + jq);
    unsigned w0 = aw0[0], w1 = aw1[0];
    float4 b0 = *(const float4*)(Bp + (size_t)bk * E + colBase + bn);
    float4 b1 = *(const float4*)(Bp + (size_t)(bk + 8) * E + colBase + bn);

    {
        int sh = jq;  // k0=0
        float s, n, v;
        float* f2a = (float*)&f2v; float* e2a = (float*)&E2v; float* g2a = (float*)&F2v;
#pragma unroll
        for (int i = 0; i < 4; i++) {
            s = f1_0 + f2a[i]; n = (s > 0.f) ? E1_0 * e2a[i] : F1_0 * g2a[i];
            v = ((w0 >> (sh + i)) & 1u) ? n : 0.f;
            rsum0 += v; As[0][jq + i][ar] = v;
            s = f1_1 + f2a[i]; n = (s > 0.f) ? E1_1 * e2a[i] : F1_1 * g2a[i];
            v = ((w1 >> (sh + i)) & 1u) ? n : 0.f;
            rsum1 += v; As[0][jq + i][ar + 64] = v;
        }
    }
    *(float4*)&Bs[0][bk][bn] = b0;
    *(float4*)&Bs[0][bk + 8][bn] = b1;
    __syncthreads();

    float acc[8][8] = {};
    int buf = 0;
    for (int k0 = 16;; k0 += 16) {
        bool last = (k0 >= Nn);
        if (!last) {
            f2v = *(const float4*)(g_f2 + base + k0 + jq);
            E2v = *(const float4*)(g_E2 + base + k0 + jq);
            F2v = *(const float4*)(g_F2 + base + k0 + jq);
            w0 = aw0[k0 >> 5];
            w1 = aw1[k0 >> 5];
            b0 = *(const float4*)(Bp + (size_t)(k0 + bk) * E + colBase + bn);
            b1 = *(const float4*)(Bp + (size_t)(k0 + bk + 8) * E + colBase + bn);
        }
#pragma unroll
        for (int kk = 0; kk < 16; kk++) {
            float a[8], bb[8];
            *(float4*)(a)      = *(float4*)&As[buf][kk][ty * 4];
            *(float4*)(a + 4)  = *(float4*)&As[buf][kk][64 + ty * 4];
            *(float4*)(bb)     = *(float4*)&Bs[buf][kk][tx * 4];
            *(float4*)(bb + 4) = *(float4*)&Bs[buf][kk][64 + tx * 4];
#pragma unroll
            for (int i = 0; i < 8; i++)
#pragma unroll
                for (int j = 0; j < 8; j++) acc[i][j] += a[i] * bb[j];
        }
        if (last) break;
        buf ^= 1;
        {
            int sh = ((k0 & 31)) + jq;  // (k0&31) in {0,16}; sh+3 <= 31
            float s, n, v;
            float* f2a = (float*)&f2v; float* e2a = (float*)&E2v; float* g2a = (float*)&F2v;
#pragma unroll
            for (int i = 0; i < 4; i++) {
                s = f1_0 + f2a[i]; n = (s > 0.f) ? E1_0 * e2a[i] : F1_0 * g2a[i];
                v = ((w0 >> (sh + i)) & 1u) ? n : 0.f;
                rsum0 += v; As[buf][jq + i][ar] = v;
                s = f1_1 + f2a[i]; n = (s > 0.f) ? E1_1 * e2a[i] : F1_1 * g2a[i];
                v = ((w1 >> (sh + i)) & 1u) ? n : 0.f;
                rsum1 += v; As[buf][jq + i][ar + 64] = v;
            }
        }
        *(float4*)&Bs[buf][bk][bn] = b0;
        *(float4*)&Bs[buf][bk + 8][bn] = b1;
        __syncthreads();
    }

    // row-sum reduction (4 threads share each row)
    atomicAdd(&Ssum[ar], rsum0);
    atomicAdd(&Ssum[ar + 64], rsum1);
    __syncthreads();

    // epilogue: normalize, elu, transposed store into g_feat
#pragma unroll
    for (int i = 0; i < 8; i++) {
        int rl = (i < 4) ? (ty * 4 + i) : (64 + ty * 4 + i - 4);
        float s = Ssum[rl];
        float scale = (s > 0.f) ? (1.0f / s) : 0.f;
        float* cr = g_feat + (size_t)(b * Nn + rowBase + rl) * (H * E) + h * E + colBase;
        float t[8];
#pragma unroll
        for (int j = 0; j < 8; j++) {
            float v = acc[i][j] * scale;
            t[j] = (v > 0.f) ? v : expm1f(v);
        }
        *(float4*)(cr + tx * 4)      = make_float4(t[0], t[1], t[2], t[3]);
        *(float4*)(cr + 64 + tx * 4) = make_float4(t[4], t[5], t[6], t[7]);
    }
}

// ============================================================
// K5: out (8192x64) = feat (8192x1024) @ W_act (1024x64) + b_act
// ============================================================
__global__ void final_gemm(const float* __restrict__ W_act,
                           const float* __restrict__ b_act,
                           float* __restrict__ out) {
    const int BM = 64, BK = 16;
    __shared__ float As[BK][BM];
    __shared__ float Bs[BK][A_];
    int rowBase = blockIdx.y * BM;
    int tid = threadIdx.x;
    int tx = tid & 15, ty = tid >> 4;
    float acc[4][4] = {};
    for (int k0 = 0; k0 < H * E; k0 += BK) {
        {
            int r = tid >> 2, c4 = tid & 3;
            float4 v = *(const float4*)(g_feat + (size_t)(rowBase + r) * (H * E) + k0 + c4 * 4);
            As[c4 * 4 + 0][r] = v.x;
            As[c4 * 4 + 1][r] = v.y;
            As[c4 * 4 + 2][r] = v.z;
            As[c4 * 4 + 3][r] = v.w;
        }
        {
            int r = tid >> 4, c4 = tid & 15;
            float4 v = *(const float4*)(W_act + (size_t)(k0 + r) * A_ + c4 * 4);
            *(float4*)&Bs[r][c4 * 4] = v;
        }
        __syncthreads();
#pragma unroll
        for (int kk = 0; kk < BK; kk++) {
            float a[4], b[4];
#pragma unroll
            for (int i = 0; i < 4; i++) a[i] = As[kk][ty * 4 + i];
            float4 bv = *(float4*)&Bs[kk][tx * 4];
            b[0] = bv.x; b[1] = bv.y; b[2] = bv.z; b[3] = bv.w;
#pragma unroll
            for (int i = 0; i < 4; i++)
#pragma unroll
                for (int j = 0; j < 4; j++) acc[i][j] += a[i] * b[j];
        }
        __syncthreads();
    }
#pragma unroll
    for (int i = 0; i < 4; i++) {
        int r = rowBase + ty * 4 + i;
        float4 bias = *(const float4*)(b_act + tx * 4);
        float4 v = make_float4(acc[i][0] + bias.x, acc[i][1] + bias.y,
                               acc[i][2] + bias.z, acc[i][3] + bias.w);
        *(float4*)(out + (size_t)r * A_ + tx * 4) = v;
    }
}

extern "C" void kernel_launch(void* const* d_in, const int* in_sizes, int n_in,
                              void* d_out, int out_size) {
    const float* x     = (const float*)d_in[0];
    const int*   adj   = (const int*)d_in[1];
    const float* W     = (const float*)d_in[2];
    const float* a1    = (const float*)d_in[3];
    const float* a2    = (const float*)d_in[4];
    const float* W_act = (const float*)d_in[5];
    const float* b_act = (const float*)d_in[6];
    float* out = (float*)d_out;

    pack_adj<<<(Bb * Nn * Nn) / 256, 256>>>(adj);
    wh_gemm<<<dim3(E / 128, BN_ROWS / 128, H), 256>>>(x, W);
    compute_f<<<(H * BN_ROWS) / 8, 256>>>(a1, a2);
    att_gemm<<<dim3(E / 128, Nn / 128, H * Bb), 256>>>();
    final_gemm<<<dim3(1, BN_ROWS / 64), 256>>>(W_act, b_act, out);
}

// round 6
// speedup vs baseline: 1.4356x; 1.2320x over previous
#include <cuda_runtime.h>
#include <math.h>
#include <stdint.h>

#define H 4
#define Bb 8
#define Nn 1024
#define INF_ 1024
#define E 256
#define A_ 64
#define BN_ROWS 8192        /* B*N */
#define ALPHA 0.2f
#define PITCH 136           /* smem row pitch: 136 % 32 == 8 -> conflict-free frags */

// ---- scratch (static device memory; no runtime allocation) ----
__device__ float g_Wh[H * BN_ROWS * E];                 // 32 MB   [h][row][e]
__device__ float g_f1[H * BN_ROWS];
__device__ float g_f2[H * BN_ROWS];
__device__ float g_E1[H * BN_ROWS];
__device__ float g_F1[H * BN_ROWS];
__device__ float g_E2[H * BN_ROWS];
__device__ float g_F2[H * BN_ROWS];
__device__ unsigned g_adjbits[Bb * Nn * (Nn / 32)];     // 1 MB packed adjacency
__device__ float g_feat[(size_t)BN_ROWS * H * E];       // 32 MB  [row][h*E+e]

// ---- tf32 helpers ----
__device__ __forceinline__ float tf32_lo(float v) {
    // hi = RZ-truncation to tf32 (what the MMA HW does to a raw f32 input)
    return v - __uint_as_float(__float_as_uint(v) & 0xFFFFE000u);
}
__device__ __forceinline__ void mma8(float c[4], const float a[4], const float b[2]) {
    asm volatile(
        "mma.sync.aligned.m16n8k8.row.col.f32.tf32.tf32.f32 "
        "{%0,%1,%2,%3}, {%4,%5,%6,%7}, {%8,%9}, {%0,%1,%2,%3};"
        : "+f"(c[0]), "+f"(c[1]), "+f"(c[2]), "+f"(c[3])
        : "r"(__float_as_uint(a[0])), "r"(__float_as_uint(a[1])),
          "r"(__float_as_uint(a[2])), "r"(__float_as_uint(a[3])),
          "r"(__float_as_uint(b[0])), "r"(__float_as_uint(b[1])));
}

// one k8 step: 16 mma tiles x 3 passes (3xTF32)
__device__ __forceinline__ void k8_step(const float (*AS)[PITCH], const float (*BS)[PITCH],
                                        int k8, int mw, int nw, int lq, int lr,
                                        float acc[4][4][4]) {
    float a[4][4], al[4][4], bf[4][2], bl[4][2];
#pragma unroll
    for (int mt = 0; mt < 4; mt++) {
        int m0 = mw + 16 * mt + lr;
        a[mt][0] = AS[k8 + lq][m0];
        a[mt][1] = AS[k8 + lq][m0 + 8];
        a[mt][2] = AS[k8 + lq + 4][m0];
        a[mt][3] = AS[k8 + lq + 4][m0 + 8];
        al[mt][0] = tf32_lo(a[mt][0]);
        al[mt][1] = tf32_lo(a[mt][1]);
        al[mt][2] = tf32_lo(a[mt][2]);
        al[mt][3] = tf32_lo(a[mt][3]);
    }
#pragma unroll
    for (int nt = 0; nt < 4; nt++) {
        int n0 = nw + 8 * nt + lr;
        bf[nt][0] = BS[k8 + lq][n0];
        bf[nt][1] = BS[k8 + lq + 4][n0];
        bl[nt][0] = tf32_lo(bf[nt][0]);
        bl[nt][1] = tf32_lo(bf[nt][1]);
    }
#pragma unroll
    for (int mt = 0; mt < 4; mt++)
#pragma unroll
        for (int nt = 0; nt < 4; nt++) mma8(acc[mt][nt], a[mt], bf[nt]);
#pragma unroll
    for (int mt = 0; mt < 4; mt++)
#pragma unroll
        for (int nt = 0; nt < 4; nt++) mma8(acc[mt][nt], a[mt], bl[nt]);
#pragma unroll
    for (int mt = 0; mt < 4; mt++)
#pragma unroll
        for (int nt = 0; nt < 4; nt++) mma8(acc[mt][nt], al[mt], bf[nt]);
}

// ============================================================
// K0: pack adjacency int32 -> bitmask
// ============================================================
__global__ void pack_adj(const int* __restrict__ adj) {
    int idx = blockIdx.x * blockDim.x + threadIdx.x;
    unsigned m = __ballot_sync(0xffffffffu, adj[idx] > 0);
    if ((idx & 31) == 0) g_adjbits[idx >> 5] = m;
}

// ============================================================
// K1: Wh = x @ W[h], tf32 mma 3x. block 128x128, k16 double-buffered.
// grid (E/128=2, BN/128=64, H=4), 256 thr.
// ============================================================
__global__ void __launch_bounds__(256) wh_gemm_mma(const float* __restrict__ x,
                                                   const float* __restrict__ W) {
    __shared__ float As[2][16][PITCH];
    __shared__ float Bs[2][16][PITCH];
    int h = blockIdx.z;
    int rowBase = blockIdx.y * 128;
    int colBase = blockIdx.x * 128;
    int tid = threadIdx.x, lane = tid & 31, wid = tid >> 5;
    int lq = lane & 3, lr = lane >> 2;
    int mw = (wid & 1) * 64, nw = (wid >> 1) * 32;

    // loader assignment
    int am = tid & 127;
    int ak1 = (tid >> 7) * 4;          // 0 or 4 (pairs with +8)
    int bk1 = tid >> 5;                // 0..7 (pairs with +8)
    int bn = (tid & 31) * 4;

    const float* Ap = x + (size_t)(rowBase + am) * INF_;
    const float* Bp = W + (size_t)h * INF_ * E + colBase;

    float4 a0r = *(const float4*)(Ap + ak1);
    float4 a1r = *(const float4*)(Ap + ak1 + 8);
    float4 b0r = *(const float4*)(Bp + (size_t)bk1 * E + bn);
    float4 b1r = *(const float4*)(Bp + (size_t)(bk1 + 8) * E + bn);
    As[0][ak1 + 0][am] = a0r.x; As[0][ak1 + 1][am] = a0r.y;
    As[0][ak1 + 2][am] = a0r.z; As[0][ak1 + 3][am] = a0r.w;
    As[0][ak1 + 8][am] = a1r.x; As[0][ak1 + 9][am] = a1r.y;
    As[0][ak1 + 10][am] = a1r.z; As[0][ak1 + 11][am] = a1r.w;
    *(float4*)&Bs[0][bk1][bn] = b0r;
    *(float4*)&Bs[0][bk1 + 8][bn] = b1r;
    __syncthreads();

    float acc[4][4][4] = {};
    for (int c = 0; c < 64; c++) {
        int cb = c & 1;
        if (c < 63) {
            int k0 = (c + 1) * 16;
            a0r = *(const float4*)(Ap + k0 + ak1);
            a1r = *(const float4*)(Ap + k0 + ak1 + 8);
            b0r = *(const float4*)(Bp + (size_t)(k0 + bk1) * E + bn);
            b1r = *(const float4*)(Bp + (size_t)(k0 + bk1 + 8) * E + bn);
        }
        k8_step(As[cb], Bs[cb], 0, mw, nw, lq, lr, acc);
        k8_step(As[cb], Bs[cb], 8, mw, nw, lq, lr, acc);
        if (c < 63) {
            int nb = cb ^ 1;
            As[nb][ak1 + 0][am] = a0r.x; As[nb][ak1 + 1][am] = a0r.y;
            As[nb][ak1 + 2][am] = a0r.z; As[nb][ak1 + 3][am] = a0r.w;
            As[nb][ak1 + 8][am] = a1r.x; As[nb][ak1 + 9][am] = a1r.y;
            As[nb][ak1 + 10][am] = a1r.z; As[nb][ak1 + 11][am] = a1r.w;
            *(float4*)&Bs[nb][bk1][bn] = b0r;
            *(float4*)&Bs[nb][bk1 + 8][bn] = b1r;
        }
        __syncthreads();
    }

    float* Cp = g_Wh + (size_t)h * BN_ROWS * E;
#pragma unroll
    for (int mt = 0; mt < 4; mt++) {
        int r = rowBase + mw + 16 * mt + lr;
#pragma unroll
        for (int nt = 0; nt < 4; nt++) {
            int cc = colBase + nw + 8 * nt + 2 * lq;
            *(float2*)(Cp + (size_t)r * E + cc) = make_float2(acc[mt][nt][0], acc[mt][nt][1]);
            *(float2*)(Cp + (size_t)(r + 8) * E + cc) = make_float2(acc[mt][nt][2], acc[mt][nt][3]);
        }
    }
}

// ============================================================
// K2: f1/f2 = Wh . a1/a2 + factored exps. Warp per row.
// ============================================================
__global__ void compute_f(const float* __restrict__ a1, const float* __restrict__ a2) {
    int r = (blockIdx.x * blockDim.x + threadIdx.x) >> 5;
    int lane = threadIdx.x & 31;
    int h = r >> 13;
    const float* wh = g_Wh + (size_t)r * E;
    const float* a1p = a1 + h * E;
    const float* a2p = a2 + h * E;
    float s1 = 0.f, s2 = 0.f;
#pragma unroll
    for (int i = 0; i < 8; i++) {
        int e = lane + i * 32;
        float v = wh[e];
        s1 += v * a1p[e];
        s2 += v * a2p[e];
    }
#pragma unroll
    for (int o = 16; o > 0; o >>= 1) {
        s1 += __shfl_xor_sync(0xffffffffu, s1, o);
        s2 += __shfl_xor_sync(0xffffffffu, s2, o);
    }
    if (lane == 0) {
        g_f1[r] = s1;
        g_f2[r] = s2;
        g_E1[r] = __expf(s1);
        g_F1[r] = __expf(ALPHA * s1);
        g_E2[r] = __expf(s2);
        g_F2[r] = __expf(ALPHA * s2);
    }
}

// ============================================================
// K3: h' = att @ Wh_b, tf32 mma 3x; att generated on the fly into
// smem [k][m]; row sums in regs; normalize + elu in epilogue.
// grid (E/128=2, Nn/128=8, H*Bb=32), 256 thr.
// ============================================================
__global__ void __launch_bounds__(256) att_gemm_mma() {
    __shared__ float As[2][16][PITCH];
    __shared__ float Bs[2][16][PITCH];
    __shared__ float Ssum2[2][128];
    int hb = blockIdx.z;
    int h = hb >> 3, b = hb & 7;
    int rowBase = blockIdx.y * 128;
    int colBase = blockIdx.x * 128;
    int base = h * BN_ROWS + b * Nn;
    int tid = threadIdx.x, lane = tid & 31, wid = tid >> 5;
    int lq = lane & 3, lr = lane >> 2;
    int mw = (wid & 1) * 64, nw = (wid >> 1) * 32;

    // generator: fixed row i per thread, j parity by tid>>7
    int ig = tid & 127;
    int jp = tid >> 7;
    int gi = base + rowBase + ig;
    float f1v = g_f1[gi], E1v = g_E1[gi], F1v = g_F1[gi];
    const unsigned* awp = g_adjbits + (size_t)(b * Nn + rowBase + ig) * (Nn / 32);
    unsigned wbits = 0;
    float rsum = 0.f;

    // B loader
    int bk1 = tid >> 5;
    int bn = (tid & 31) * 4;
    const float* Bp = g_Wh + ((size_t)h * BN_ROWS + b * Nn) * E + colBase;

#define GEN(nb, k0)                                                            \
    do {                                                                       \
        if (((k0) & 31) == 0) wbits = awp[(k0) >> 5];                          \
        _Pragma("unroll")                                                      \
        for (int it = 0; it < 8; it++) {                                       \
            int jl = 2 * it + jp;                                              \
            int j = (k0) + jl;                                                 \
            float f2 = g_f2[base + j];                                         \
            float e2 = g_E2[base + j];                                         \
            float q2 = g_F2[base + j];                                         \
            float s = f1v + f2;                                                \
            float n = (s > 0.f) ? E1v * e2 : F1v * q2;                         \
            float v = ((wbits >> (j & 31)) & 1u) ? n : 0.f;                    \
            rsum += v;                                                         \
            As[nb][jl][ig] = v;                                                \
        }                                                                      \
    } while (0)

    // prologue
    GEN(0, 0);
    float4 b0r = *(const float4*)(Bp + (size_t)bk1 * E + bn);
    float4 b1r = *(const float4*)(Bp + (size_t)(bk1 + 8) * E + bn);
    *(float4*)&Bs[0][bk1][bn] = b0r;
    *(float4*)&Bs[0][bk1 + 8][bn] = b1r;
    __syncthreads();

    float acc[4][4][4] = {};
    for (int c = 0; c < 64; c++) {
        int cb = c & 1;
        if (c < 63) {
            int k0 = (c + 1) * 16;
            b0r = *(const float4*)(Bp + (size_t)(k0 + bk1) * E + bn);
            b1r = *(const float4*)(Bp + (size_t)(k0 + bk1 + 8) * E + bn);
        }
        k8_step(As[cb], Bs[cb], 0, mw, nw, lq, lr, acc);
        k8_step(As[cb], Bs[cb], 8, mw, nw, lq, lr, acc);
        if (c < 63) {
            int nb = cb ^ 1;
            GEN(nb, (c + 1) * 16);
            *(float4*)&Bs[nb][bk1][bn] = b0r;
            *(float4*)&Bs[nb][bk1 + 8][bn] = b1r;
        }
        __syncthreads();
    }

    Ssum2[jp][ig] = rsum;
    __syncthreads();

#pragma unroll
    for (int mt = 0; mt < 4; mt++) {
        int rl = mw + 16 * mt + lr;
        float S0 = Ssum2[0][rl] + Ssum2[1][rl];
        float S8 = Ssum2[0][rl + 8] + Ssum2[1][rl + 8];
        float sc0 = (S0 > 0.f) ? (1.0f / S0) : 0.f;
        float sc8 = (S8 > 0.f) ? (1.0f / S8) : 0.f;
        float* f0 = g_feat + (size_t)(b * Nn + rowBase + rl) * (H * E) + h * E + colBase;
        float* f8 = g_feat + (size_t)(b * Nn + rowBase + rl + 8) * (H * E) + h * E + colBase;
#pragma unroll
        for (int nt = 0; nt < 4; nt++) {
            int cc = nw + 8 * nt + 2 * lq;
            float v0 = acc[mt][nt][0] * sc0;
            float v1 = acc[mt][nt][1] * sc0;
            float v2 = acc[mt][nt][2] * sc8;
            float v3 = acc[mt][nt][3] * sc8;
            v0 = (v0 > 0.f) ? v0 : expm1f(v0);
            v1 = (v1 > 0.f) ? v1 : expm1f(v1);
            v2 = (v2 > 0.f) ? v2 : expm1f(v2);
            v3 = (v3 > 0.f) ? v3 : expm1f(v3);
            *(float2*)(f0 + cc) = make_float2(v0, v1);
            *(float2*)(f8 + cc) = make_float2(v2, v3);
        }
    }
#undef GEN
}

// ============================================================
// K5: out (8192x64) = feat (8192x1024) @ W_act (1024x64) + b_act
// ============================================================
__global__ void final_gemm(const float* __restrict__ W_act,
                           const float* __restrict__ b_act,
                           float* __restrict__ out) {
    const int BM = 64, BK = 16;
    __shared__ float As[BK][BM];
    __shared__ float Bs[BK][A_];
    int rowBase = blockIdx.y * BM;
    int tid = threadIdx.x;
    int tx = tid & 15, ty = tid >> 4;
    float acc[4][4] = {};
    for (int k0 = 0; k0 < H * E; k0 += BK) {
        {
            int r = tid >> 2, c4 = tid & 3;
            float4 v = *(const float4*)(g_feat + (size_t)(rowBase + r) * (H * E) + k0 + c4 * 4);
            As[c4 * 4 + 0][r] = v.x;
            As[c4 * 4 + 1][r] = v.y;
            As[c4 * 4 + 2][r] = v.z;
            As[c4 * 4 + 3][r] = v.w;
        }
        {
            int r = tid >> 4, c4 = tid & 15;
            float4 v = *(const float4*)(W_act + (size_t)(k0 + r) * A_ + c4 * 4);
            *(float4*)&Bs[r][c4 * 4] = v;
        }
        __syncthreads();
#pragma unroll
        for (int kk = 0; kk < BK; kk++) {
            float a[4], bv2[4];
#pragma unroll
            for (int i = 0; i < 4; i++) a[i] = As[kk][ty * 4 + i];
            float4 bv = *(float4*)&Bs[kk][tx * 4];
            bv2[0] = bv.x; bv2[1] = bv.y; bv2[2] = bv.z; bv2[3] = bv.w;
#pragma unroll
            for (int i = 0; i < 4; i++)
#pragma unroll
                for (int j = 0; j < 4; j++) acc[i][j] += a[i] * bv2[j];
        }
        __syncthreads();
    }
#pragma unroll
    for (int i = 0; i < 4; i++) {
        int r = rowBase + ty * 4 + i;
        float4 bias = *(const float4*)(b_act + tx * 4);
        float4 v = make_float4(acc[i][0] + bias.x, acc[i][1] + bias.y,
                               acc[i][2] + bias.z, acc[i][3] + bias.w);
        *(float4*)(out + (size_t)r * A_ + tx * 4) = v;
    }
}

extern "C" void kernel_launch(void* const* d_in, const int* in_sizes, int n_in,
                              void* d_out, int out_size) {
    const float* x     = (const float*)d_in[0];
    const int*   adj   = (const int*)d_in[1];
    const float* W     = (const float*)d_in[2];
    const float* a1    = (const float*)d_in[3];
    const float* a2    = (const float*)d_in[4];
    const float* W_act = (const float*)d_in[5];
    const float* b_act = (const float*)d_in[6];
    float* out = (float*)d_out;

    pack_adj<<<(Bb * Nn * Nn) / 256, 256>>>(adj);
    wh_gemm_mma<<<dim3(E / 128, BN_ROWS / 128, H), 256>>>(x, W);
    compute_f<<<(H * BN_ROWS) / 8, 256>>>(a1, a2);
    att_gemm_mma<<<dim3(E / 128, Nn / 128, H * Bb), 256>>>();
    final_gemm<<<dim3(1, BN_ROWS / 64), 256>>>(W_act, b_act, out);
}